// round 13
// baseline (speedup 1.0000x reference)
#include <cuda_runtime.h>
#include <cuda_fp16.h>
#include <mma.h>

using namespace nvcuda;

#define V    50000
#define E    800000
#define BB   2
#define FIN  64
#define FOUT 64
#define KK   4
#define NB   ((V + 1023) / 1024)   // 49 scan blocks
#define FULLM 0xffffffffu

// ---------------- device scratch (allocation-free rule: __device__ globals) ----
// fp16 state. Per vertex v: 64 uints = 128 halves;
//   uint j in [0,32): b=0, features (2j, 2j+1); j in [32,64): b=1.
__device__ unsigned g_H0[V * 64];
__device__ unsigned g_H1[V * 64];
__device__ unsigned g_H2[V * 64];
__device__ unsigned g_H3[V * 64];
__device__ unsigned g_Wh[KK * FIN * FOUT / 2];   // fp16 weights, 2 per uint
__device__ int      g_counts[V];     // zero-init; re-zeroed by scan_write
__device__ int      g_rowptr[V + 1];
__device__ int      g_bsums[NB];
__device__ int      g_rank[E];       // edge's within-row rank (from hist atomic)
__device__ int2     g_edge[E];       // (col, float-bits of val), row-sorted

__device__ __forceinline__ unsigned* hsel(int k) {
    switch (k) {
        case 0: return g_H0;
        case 1: return g_H1;
        case 2: return g_H2;
        default: return g_H3;
    }
}

// ---------------- 1) fused front: transpose+mirror + histogram(+rank) + W->fp16
#define TRANS_BLOCKS ((V * 32) / 256)            // 6250
#define HIST_BLOCKS  (E / 256)                   // 3125
#define WCONV_BLOCKS ((KK * FIN * FOUT / 2) / 256)   // 32
__global__ void front_kernel(const float* __restrict__ in,
                             const float* __restrict__ wt,
                             const int* __restrict__ rows) {
    int blk = blockIdx.x;
    if (blk < TRANS_BLOCKS) {
        int idx = blk * 256 + threadIdx.x;   // over V*32 f-pairs
        int v = idx >> 5;
        int fp = idx & 31;                   // features (2fp, 2fp+1)
        float2 a = __ldg(&reinterpret_cast<const float2*>(in)[v * 32 + fp]);          // b=0
        float2 c = __ldg(&reinterpret_cast<const float2*>(in)[V * 32 + v * 32 + fp]); // b=1
        __half2 h0 = __floats2half2_rn(a.x, a.y);
        __half2 h1 = __floats2half2_rn(c.x, c.y);
        g_H0[v * 64 + fp]      = *reinterpret_cast<unsigned*>(&h0);
        g_H0[v * 64 + 32 + fp] = *reinterpret_cast<unsigned*>(&h1);
    } else if (blk < TRANS_BLOCKS + HIST_BLOCKS) {
        int e = (blk - TRANS_BLOCKS) * 256 + threadIdx.x;
        int rr = __ldg(&rows[e]);
        g_rank[e] = atomicAdd(&g_counts[rr], 1);   // rank within row, for free
    } else {
        int i = (blk - TRANS_BLOCKS - HIST_BLOCKS) * 256 + threadIdx.x;  // over 8192
        __half2 h = __floats2half2_rn(wt[2 * i], wt[2 * i + 1]);
        g_Wh[i] = *reinterpret_cast<unsigned*>(&h);
    }
}

// ---------------- 2) CSR build ------------------------------------------------
__global__ void scan_reduce_kernel() {
    __shared__ int swarp[32];
    int tid = threadIdx.x;
    int i = blockIdx.x * 1024 + tid;
    int v = (i < V) ? g_counts[i] : 0;
    for (int o = 16; o > 0; o >>= 1) v += __shfl_down_sync(FULLM, v, o);
    if ((tid & 31) == 0) swarp[tid >> 5] = v;
    __syncthreads();
    if (tid < 32) {
        int s = swarp[tid];
        for (int o = 16; o > 0; o >>= 1) s += __shfl_down_sync(FULLM, s, o);
        if (tid == 0) g_bsums[blockIdx.x] = s;
    }
}

__global__ void scan_write_kernel() {
    __shared__ int s[1024];
    __shared__ int boff;
    int tid = threadIdx.x;
    if (tid == 0) {
        int run = 0;
        for (int j = 0; j < NB; j++) {
            if (j == (int)blockIdx.x) boff = run;
            run += g_bsums[j];
        }
        if (blockIdx.x == 0) g_rowptr[V] = run;   // == E
    }
    int i = blockIdx.x * 1024 + tid;
    int v = (i < V) ? g_counts[i] : 0;
    s[tid] = v;
    __syncthreads();
#pragma unroll
    for (int o = 1; o < 1024; o <<= 1) {
        int t = (tid >= o) ? s[tid - o] : 0;
        __syncthreads();
        s[tid] += t;
        __syncthreads();
    }
    if (i < V) {
        g_rowptr[i] = s[tid] - v + boff;
        g_counts[i] = 0;     // restore invariant for next replay
    }
}

// atomic-free scatter: p = rowptr[row] + rank[e]; pure load->store, full MLP
__global__ void scatter_kernel(const float* __restrict__ vals,
                               const int* __restrict__ rows,
                               const int* __restrict__ cols) {
    int e = blockIdx.x * blockDim.x + threadIdx.x;
    if (e >= E) return;
    int rr = __ldg(&rows[e]);
    int p  = __ldg(&g_rowptr[rr]) + g_rank[e];
    g_edge[p] = make_int2(__ldg(&cols[e]), __float_as_int(__ldg(&vals[e])));
}

// ---------------- 3) CSR SpMM (r9 structure, 4-way unroll) --------------------
// One warp per row. Lane l owns halves (4l..4l+3): one LDG.64 per edge.
// Edge metadata loads are warp-uniform broadcasts. 4 independent edge+gather
// chains in flight per iteration.
__device__ __forceinline__ void accum4(float4& a, uint2 rr, float v) {
    float2 p0 = __half22float2(*reinterpret_cast<__half2*>(&rr.x));
    float2 p1 = __half22float2(*reinterpret_cast<__half2*>(&rr.y));
    a.x = fmaf(v, p0.x, a.x);
    a.y = fmaf(v, p0.y, a.y);
    a.z = fmaf(v, p1.x, a.z);
    a.w = fmaf(v, p1.y, a.w);
}

__global__ void spmm_csr_kernel(int ksrc, int kdst, int kprev,
                                float alpha, float beta) {
    int gtid = blockIdx.x * blockDim.x + threadIdx.x;
    int r = gtid >> 5;
    int lane = gtid & 31;
    if (r >= V) return;

    const uint2* __restrict__ hx = reinterpret_cast<const uint2*>(hsel(ksrc));
    int s = g_rowptr[r];
    int e = g_rowptr[r + 1];

    float4 acc0 = make_float4(0.f, 0.f, 0.f, 0.f);
    float4 acc1 = make_float4(0.f, 0.f, 0.f, 0.f);
    float4 acc2 = make_float4(0.f, 0.f, 0.f, 0.f);
    float4 acc3 = make_float4(0.f, 0.f, 0.f, 0.f);

    int i = s;
    for (; i + 4 <= e; i += 4) {
        int2 e0 = __ldg(&g_edge[i]);
        int2 e1 = __ldg(&g_edge[i + 1]);
        int2 e2 = __ldg(&g_edge[i + 2]);
        int2 e3 = __ldg(&g_edge[i + 3]);
        uint2 r0 = __ldg(&hx[e0.x * 32 + lane]);
        uint2 r1 = __ldg(&hx[e1.x * 32 + lane]);
        uint2 r2 = __ldg(&hx[e2.x * 32 + lane]);
        uint2 r3 = __ldg(&hx[e3.x * 32 + lane]);
        accum4(acc0, r0, __int_as_float(e0.y));
        accum4(acc1, r1, __int_as_float(e1.y));
        accum4(acc2, r2, __int_as_float(e2.y));
        accum4(acc3, r3, __int_as_float(e3.y));
    }
    for (; i < e; i++) {
        int2 e0 = __ldg(&g_edge[i]);
        uint2 r0 = __ldg(&hx[e0.x * 32 + lane]);
        accum4(acc0, r0, __int_as_float(e0.y));
    }
    acc0.x += acc1.x + acc2.x + acc3.x;
    acc0.y += acc1.y + acc2.y + acc3.y;
    acc0.z += acc1.z + acc2.z + acc3.z;
    acc0.w += acc1.w + acc2.w + acc3.w;

    float4 o;
    if (beta != 0.f) {
        uint2 rp = __ldg(&reinterpret_cast<const uint2*>(hsel(kprev))[r * 32 + lane]);
        float2 p0 = __half22float2(*reinterpret_cast<__half2*>(&rp.x));
        float2 p1 = __half22float2(*reinterpret_cast<__half2*>(&rp.y));
        o.x = fmaf(beta, p0.x, alpha * acc0.x);
        o.y = fmaf(beta, p0.y, alpha * acc0.y);
        o.z = fmaf(beta, p1.x, alpha * acc0.z);
        o.w = fmaf(beta, p1.y, alpha * acc0.w);
    } else {
        o.x = alpha * acc0.x; o.y = alpha * acc0.y;
        o.z = alpha * acc0.z; o.w = alpha * acc0.w;
    }

    uint2 m;
    __half2 m0 = __floats2half2_rn(o.x, o.y);
    __half2 m1 = __floats2half2_rn(o.z, o.w);
    m.x = *reinterpret_cast<unsigned*>(&m0);
    m.y = *reinterpret_cast<unsigned*>(&m1);
    reinterpret_cast<uint2*>(hsel(kdst))[r * 32 + lane] = m;
}

// ---------------- 4) tensor-core GEMM ----------------------------------------
#define AP 72   // padded half stride
__global__ void gemm_kernel(const float* __restrict__ bias,
                            float* __restrict__ out) {
    __shared__ __align__(16) char sbuf[35840];
    unsigned* As_u = reinterpret_cast<unsigned*>(sbuf);            // 128*36*4
    unsigned* Bs_u = reinterpret_cast<unsigned*>(sbuf + 18432);    //  64*36*4
    float*    Cs   = reinterpret_cast<float*>(sbuf);               // epilogue

    int tid = threadIdx.x;
    int w = tid >> 5;
    int lane = tid & 31;
    int rho0 = blockIdx.x * 128;

    wmma::fragment<wmma::accumulator, 16, 16, 16, float> acc[4];
#pragma unroll
    for (int nt = 0; nt < 4; nt++) wmma::fill_fragment(acc[nt], 0.f);

    for (int k = 0; k < KK; k++) {
        __syncthreads();
        const unsigned* m = hsel(k);
#pragma unroll
        for (int it = 0; it < 16; it++) {        // A: 128 rho-rows x 32 uints
            int i = tid + it * 256;
            int r = i >> 5, cu = i & 31;
            int rho = rho0 + r;
            unsigned val = 0u;
            if (rho < 2 * V)
                val = __ldcg(&m[(rho >> 1) * 64 + (rho & 1) * 32 + cu]);
            As_u[r * 36 + cu] = val;
        }
#pragma unroll
        for (int it = 0; it < 8; it++) {         // B: 64 f-rows x 32 uints
            int i = tid + it * 256;
            int f = i >> 5, cu = i & 31;
            Bs_u[f * 36 + cu] = __ldg(&g_Wh[(f * 4 + k) * 32 + cu]);
        }
        __syncthreads();

        const __half* As = reinterpret_cast<const __half*>(As_u);
        const __half* Bs = reinterpret_cast<const __half*>(Bs_u);
#pragma unroll
        for (int kc = 0; kc < 4; kc++) {
            wmma::fragment<wmma::matrix_a, 16, 16, 16, __half, wmma::row_major> af;
            wmma::load_matrix_sync(af, As + (w * 16) * AP + kc * 16, AP);
#pragma unroll
            for (int nt = 0; nt < 4; nt++) {
                wmma::fragment<wmma::matrix_b, 16, 16, 16, __half, wmma::row_major> bf;
                wmma::load_matrix_sync(bf, Bs + (kc * 16) * AP + nt * 16, AP);
                wmma::mma_sync(acc[nt], af, bf, acc[nt]);
            }
        }
    }

    __syncthreads();   // done with As/Bs; reuse sbuf as Cs
    float* Cw = Cs + w * 16 * 68;
#pragma unroll
    for (int nt = 0; nt < 4; nt++)
        wmma::store_matrix_sync(Cw + nt * 16, acc[nt], 68, wmma::mem_row_major);
    __syncwarp();

    const float4* b4 = reinterpret_cast<const float4*>(bias);
    float4* out4 = reinterpret_cast<float4*>(out);
#pragma unroll
    for (int j = 0; j < 8; j++) {
        int idx = lane + j * 32;            // 16 rows x 16 float4
        int r = idx >> 4, c4 = idx & 15;
        int rho = rho0 + w * 16 + r;
        if (rho < 2 * V) {
            int v = rho >> 1, b = rho & 1;
            float4 cv = *reinterpret_cast<const float4*>(&Cw[r * 68 + c4 * 4]);
            float4 bb = __ldg(&b4[c4]);
            out4[(b * V + v) * 16 + c4] =
                make_float4(cv.x + bb.x, cv.y + bb.y, cv.z + bb.z, cv.w + bb.w);
        }
    }
}

// ---------------- launch ------------------------------------------------------
extern "C" void kernel_launch(void* const* d_in, const int* in_sizes, int n_in,
                              void* d_out, int out_size) {
    const float* inputs   = (const float*)d_in[0];   // [B, V, FIN]
    const float* weight   = (const float*)d_in[1];   // [K, FIN, FOUT]
    const float* bias     = (const float*)d_in[2];   // [FOUT]
    const float* lap_vals = (const float*)d_in[3];   // [E]
    const int*   lap_rows = (const int*)d_in[4];     // [E]
    const int*   lap_cols = (const int*)d_in[5];     // [E]
    float*       out      = (float*)d_out;           // [B, V, FOUT]

    front_kernel<<<TRANS_BLOCKS + HIST_BLOCKS + WCONV_BLOCKS, 256>>>(inputs, weight, lap_rows);
    scan_reduce_kernel<<<NB, 1024>>>();
    scan_write_kernel<<<NB, 1024>>>();
    scatter_kernel<<<(E + 255) / 256, 256>>>(lap_vals, lap_rows, lap_cols);

    const int spmm_blocks = (V * 32 + 255) / 256;
    spmm_csr_kernel<<<spmm_blocks, 256>>>(0, 1, 0, 1.f, 0.f);    // x1 = L x0
    spmm_csr_kernel<<<spmm_blocks, 256>>>(1, 2, 0, 2.f, -1.f);   // x2 = 2Lx1 - x0
    spmm_csr_kernel<<<spmm_blocks, 256>>>(2, 3, 1, 2.f, -1.f);   // x3 = 2Lx2 - x1

    gemm_kernel<<<(2 * V + 127) / 128, 256>>>(bias, out);
}

// round 17
// speedup vs baseline: 1.0951x; 1.0951x over previous
#include <cuda_runtime.h>
#include <cuda_fp16.h>
#include <mma.h>

using namespace nvcuda;

#define V    50000
#define E    800000
#define BB   2
#define FIN  64
#define FOUT 64
#define KK   4
#define NB   ((V + 1023) / 1024)   // 49 scan blocks
#define FULLM 0xffffffffu

// ---------------- device scratch (allocation-free rule: __device__ globals) ----
// fp16 state. Per vertex v: 64 uints = 128 halves;
//   uint j in [0,32): b=0, features (2j, 2j+1); j in [32,64): b=1.
__device__ unsigned g_H0[V * 64];
__device__ unsigned g_H1[V * 64];
__device__ unsigned g_H2[V * 64];
__device__ unsigned g_H3[V * 64];
__device__ unsigned g_Wh[KK * FIN * FOUT / 2];   // fp16 weights, 2 per uint
__device__ int      g_counts[V];     // zero-init; re-zeroed by scan_write
__device__ int      g_rowptr[V + 1];
__device__ int      g_bsums[NB];
__device__ int      g_rank[E];       // edge's within-row rank (from hist atomic)
__device__ int2     g_edge[E];       // (col, float-bits of val), row-sorted

__device__ __forceinline__ unsigned* hsel(int k) {
    switch (k) {
        case 0: return g_H0;
        case 1: return g_H1;
        case 2: return g_H2;
        default: return g_H3;
    }
}

// ---------------- 1) fused front: transpose+mirror + histogram(+rank) + W->fp16
#define TRANS_BLOCKS ((V * 32) / 256)            // 6250
#define HIST_BLOCKS  (E / 256)                   // 3125
#define WCONV_BLOCKS ((KK * FIN * FOUT / 2) / 256)   // 32
__global__ void front_kernel(const float* __restrict__ in,
                             const float* __restrict__ wt,
                             const int* __restrict__ rows) {
    int blk = blockIdx.x;
    if (blk < TRANS_BLOCKS) {
        int idx = blk * 256 + threadIdx.x;   // over V*32 f-pairs
        int v = idx >> 5;
        int fp = idx & 31;                   // features (2fp, 2fp+1)
        float2 a = __ldg(&reinterpret_cast<const float2*>(in)[v * 32 + fp]);          // b=0
        float2 c = __ldg(&reinterpret_cast<const float2*>(in)[V * 32 + v * 32 + fp]); // b=1
        __half2 h0 = __floats2half2_rn(a.x, a.y);
        __half2 h1 = __floats2half2_rn(c.x, c.y);
        g_H0[v * 64 + fp]      = *reinterpret_cast<unsigned*>(&h0);
        g_H0[v * 64 + 32 + fp] = *reinterpret_cast<unsigned*>(&h1);
    } else if (blk < TRANS_BLOCKS + HIST_BLOCKS) {
        int e = (blk - TRANS_BLOCKS) * 256 + threadIdx.x;
        int rr = __ldg(&rows[e]);
        g_rank[e] = atomicAdd(&g_counts[rr], 1);   // rank within row, for free
    } else {
        int i = (blk - TRANS_BLOCKS - HIST_BLOCKS) * 256 + threadIdx.x;  // over 8192
        __half2 h = __floats2half2_rn(wt[2 * i], wt[2 * i + 1]);
        g_Wh[i] = *reinterpret_cast<unsigned*>(&h);
    }
}

// ---------------- 2) CSR build ------------------------------------------------
__global__ void scan_reduce_kernel() {
    __shared__ int swarp[32];
    int tid = threadIdx.x;
    int i = blockIdx.x * 1024 + tid;
    int v = (i < V) ? g_counts[i] : 0;
    for (int o = 16; o > 0; o >>= 1) v += __shfl_down_sync(FULLM, v, o);
    if ((tid & 31) == 0) swarp[tid >> 5] = v;
    __syncthreads();
    if (tid < 32) {
        int s = swarp[tid];
        for (int o = 16; o > 0; o >>= 1) s += __shfl_down_sync(FULLM, s, o);
        if (tid == 0) g_bsums[blockIdx.x] = s;
    }
}

__global__ void scan_write_kernel() {
    __shared__ int s[1024];
    __shared__ int boff;
    int tid = threadIdx.x;
    if (tid == 0) {
        int run = 0;
        for (int j = 0; j < NB; j++) {
            if (j == (int)blockIdx.x) boff = run;
            run += g_bsums[j];
        }
        if (blockIdx.x == 0) g_rowptr[V] = run;   // == E
    }
    int i = blockIdx.x * 1024 + tid;
    int v = (i < V) ? g_counts[i] : 0;
    s[tid] = v;
    __syncthreads();
#pragma unroll
    for (int o = 1; o < 1024; o <<= 1) {
        int t = (tid >= o) ? s[tid - o] : 0;
        __syncthreads();
        s[tid] += t;
        __syncthreads();
    }
    if (i < V) {
        g_rowptr[i] = s[tid] - v + boff;
        g_counts[i] = 0;     // restore invariant for next replay
    }
}

// atomic-free scatter: p = rowptr[row] + rank[e]; pure load->store, full MLP
__global__ void scatter_kernel(const float* __restrict__ vals,
                               const int* __restrict__ rows,
                               const int* __restrict__ cols) {
    int e = blockIdx.x * blockDim.x + threadIdx.x;
    if (e >= E) return;
    int rr = __ldg(&rows[e]);
    int p  = __ldg(&g_rowptr[rr]) + g_rank[e];
    g_edge[p] = make_int2(__ldg(&cols[e]), __float_as_int(__ldg(&vals[e])));
}

// ---------------- 3) CSR SpMM (exact r9 structure: 2-way unroll) --------------
// One warp per row. Lane l owns halves (4l..4l+3) of the 128-half vertex row:
// ONE LDG.64 per edge per lane (256B contiguous per edge). prev also fp16.
__global__ void spmm_csr_kernel(int ksrc, int kdst, int kprev,
                                float alpha, float beta) {
    int gtid = blockIdx.x * blockDim.x + threadIdx.x;
    int r = gtid >> 5;
    int lane = gtid & 31;
    if (r >= V) return;

    const uint2* __restrict__ hx = reinterpret_cast<const uint2*>(hsel(ksrc));
    int s = g_rowptr[r];
    int e = g_rowptr[r + 1];

    float4 acc0 = make_float4(0.f, 0.f, 0.f, 0.f);
    float4 acc1 = make_float4(0.f, 0.f, 0.f, 0.f);
    int i = s;
    for (; i + 1 < e; i += 2) {
        int2 e0 = __ldg(&g_edge[i]);
        int2 e1 = __ldg(&g_edge[i + 1]);
        float v0 = __int_as_float(e0.y);
        float v1 = __int_as_float(e1.y);
        uint2 ra = __ldg(&hx[e0.x * 32 + lane]);
        uint2 rb = __ldg(&hx[e1.x * 32 + lane]);
        float2 a0 = __half22float2(*reinterpret_cast<__half2*>(&ra.x));
        float2 a1 = __half22float2(*reinterpret_cast<__half2*>(&ra.y));
        float2 b0 = __half22float2(*reinterpret_cast<__half2*>(&rb.x));
        float2 b1 = __half22float2(*reinterpret_cast<__half2*>(&rb.y));
        acc0.x = fmaf(v0, a0.x, acc0.x);
        acc0.y = fmaf(v0, a0.y, acc0.y);
        acc0.z = fmaf(v0, a1.x, acc0.z);
        acc0.w = fmaf(v0, a1.y, acc0.w);
        acc1.x = fmaf(v1, b0.x, acc1.x);
        acc1.y = fmaf(v1, b0.y, acc1.y);
        acc1.z = fmaf(v1, b1.x, acc1.z);
        acc1.w = fmaf(v1, b1.y, acc1.w);
    }
    if (i < e) {
        int2 e0 = __ldg(&g_edge[i]);
        float v0 = __int_as_float(e0.y);
        uint2 ra = __ldg(&hx[e0.x * 32 + lane]);
        float2 a0 = __half22float2(*reinterpret_cast<__half2*>(&ra.x));
        float2 a1 = __half22float2(*reinterpret_cast<__half2*>(&ra.y));
        acc0.x = fmaf(v0, a0.x, acc0.x);
        acc0.y = fmaf(v0, a0.y, acc0.y);
        acc0.z = fmaf(v0, a1.x, acc0.z);
        acc0.w = fmaf(v0, a1.y, acc0.w);
    }
    acc0.x += acc1.x; acc0.y += acc1.y; acc0.z += acc1.z; acc0.w += acc1.w;

    float4 o;
    if (beta != 0.f) {
        uint2 rp = __ldg(&reinterpret_cast<const uint2*>(hsel(kprev))[r * 32 + lane]);
        float2 p0 = __half22float2(*reinterpret_cast<__half2*>(&rp.x));
        float2 p1 = __half22float2(*reinterpret_cast<__half2*>(&rp.y));
        o.x = fmaf(beta, p0.x, alpha * acc0.x);
        o.y = fmaf(beta, p0.y, alpha * acc0.y);
        o.z = fmaf(beta, p1.x, alpha * acc0.z);
        o.w = fmaf(beta, p1.y, alpha * acc0.w);
    } else {
        o.x = alpha * acc0.x; o.y = alpha * acc0.y;
        o.z = alpha * acc0.z; o.w = alpha * acc0.w;
    }

    uint2 m;
    __half2 m0 = __floats2half2_rn(o.x, o.y);
    __half2 m1 = __floats2half2_rn(o.z, o.w);
    m.x = *reinterpret_cast<unsigned*>(&m0);
    m.y = *reinterpret_cast<unsigned*>(&m1);
    reinterpret_cast<uint2*>(hsel(kdst))[r * 32 + lane] = m;
}

// ---------------- 4) tensor-core GEMM ----------------------------------------
#define AP 72   // padded half stride
__global__ void gemm_kernel(const float* __restrict__ bias,
                            float* __restrict__ out) {
    __shared__ __align__(16) char sbuf[35840];
    unsigned* As_u = reinterpret_cast<unsigned*>(sbuf);            // 128*36*4
    unsigned* Bs_u = reinterpret_cast<unsigned*>(sbuf + 18432);    //  64*36*4
    float*    Cs   = reinterpret_cast<float*>(sbuf);               // epilogue

    int tid = threadIdx.x;
    int w = tid >> 5;
    int lane = tid & 31;
    int rho0 = blockIdx.x * 128;

    wmma::fragment<wmma::accumulator, 16, 16, 16, float> acc[4];
#pragma unroll
    for (int nt = 0; nt < 4; nt++) wmma::fill_fragment(acc[nt], 0.f);

    for (int k = 0; k < KK; k++) {
        __syncthreads();
        const unsigned* m = hsel(k);
#pragma unroll
        for (int it = 0; it < 16; it++) {        // A: 128 rho-rows x 32 uints
            int i = tid + it * 256;
            int r = i >> 5, cu = i & 31;
            int rho = rho0 + r;
            unsigned val = 0u;
            if (rho < 2 * V)
                val = __ldcg(&m[(rho >> 1) * 64 + (rho & 1) * 32 + cu]);
            As_u[r * 36 + cu] = val;
        }
#pragma unroll
        for (int it = 0; it < 8; it++) {         // B: 64 f-rows x 32 uints
            int i = tid + it * 256;
            int f = i >> 5, cu = i & 31;
            Bs_u[f * 36 + cu] = __ldg(&g_Wh[(f * 4 + k) * 32 + cu]);
        }
        __syncthreads();

        const __half* As = reinterpret_cast<const __half*>(As_u);
        const __half* Bs = reinterpret_cast<const __half*>(Bs_u);
#pragma unroll
        for (int kc = 0; kc < 4; kc++) {
            wmma::fragment<wmma::matrix_a, 16, 16, 16, __half, wmma::row_major> af;
            wmma::load_matrix_sync(af, As + (w * 16) * AP + kc * 16, AP);
#pragma unroll
            for (int nt = 0; nt < 4; nt++) {
                wmma::fragment<wmma::matrix_b, 16, 16, 16, __half, wmma::row_major> bf;
                wmma::load_matrix_sync(bf, Bs + (kc * 16) * AP + nt * 16, AP);
                wmma::mma_sync(acc[nt], af, bf, acc[nt]);
            }
        }
    }

    __syncthreads();   // done with As/Bs; reuse sbuf as Cs
    float* Cw = Cs + w * 16 * 68;
#pragma unroll
    for (int nt = 0; nt < 4; nt++)
        wmma::store_matrix_sync(Cw + nt * 16, acc[nt], 68, wmma::mem_row_major);
    __syncwarp();

    const float4* b4 = reinterpret_cast<const float4*>(bias);
    float4* out4 = reinterpret_cast<float4*>(out);
#pragma unroll
    for (int j = 0; j < 8; j++) {
        int idx = lane + j * 32;            // 16 rows x 16 float4
        int r = idx >> 4, c4 = idx & 15;
        int rho = rho0 + w * 16 + r;
        if (rho < 2 * V) {
            int v = rho >> 1, b = rho & 1;
            float4 cv = *reinterpret_cast<const float4*>(&Cw[r * 68 + c4 * 4]);
            float4 bb = __ldg(&b4[c4]);
            out4[(b * V + v) * 16 + c4] =
                make_float4(cv.x + bb.x, cv.y + bb.y, cv.z + bb.z, cv.w + bb.w);
        }
    }
}

// ---------------- launch ------------------------------------------------------
extern "C" void kernel_launch(void* const* d_in, const int* in_sizes, int n_in,
                              void* d_out, int out_size) {
    const float* inputs   = (const float*)d_in[0];   // [B, V, FIN]
    const float* weight   = (const float*)d_in[1];   // [K, FIN, FOUT]
    const float* bias     = (const float*)d_in[2];   // [FOUT]
    const float* lap_vals = (const float*)d_in[3];   // [E]
    const int*   lap_rows = (const int*)d_in[4];     // [E]
    const int*   lap_cols = (const int*)d_in[5];     // [E]
    float*       out      = (float*)d_out;           // [B, V, FOUT]

    front_kernel<<<TRANS_BLOCKS + HIST_BLOCKS + WCONV_BLOCKS, 256>>>(inputs, weight, lap_rows);
    scan_reduce_kernel<<<NB, 1024>>>();
    scan_write_kernel<<<NB, 1024>>>();
    scatter_kernel<<<(E + 255) / 256, 256>>>(lap_vals, lap_rows, lap_cols);

    const int spmm_blocks = (V * 32 + 255) / 256;
    spmm_csr_kernel<<<spmm_blocks, 256>>>(0, 1, 0, 1.f, 0.f);    // x1 = L x0
    spmm_csr_kernel<<<spmm_blocks, 256>>>(1, 2, 0, 2.f, -1.f);   // x2 = 2Lx1 - x0
    spmm_csr_kernel<<<spmm_blocks, 256>>>(2, 3, 1, 2.f, -1.f);   // x3 = 2Lx2 - x1

    gemm_kernel<<<(2 * V + 127) / 128, 256>>>(bias, out);
}